// round 4
// baseline (speedup 1.0000x reference)
#include <cuda_runtime.h>
#include <cstdint>

typedef unsigned long long ull;

#define BB    8192
#define LL    128
#define OO    512
#define KK    8
#define HH    20

// Transposed per-o weight layout in shared (dup f32x2 pairs), OSTRIDE=642 pairs:
//  [0,200)   : 20 blocks of 10 pairs: [W1[0..8][j], b1[j]]      (j-th L1 neuron)
//  [200,640) : 20 blocks of 22 pairs: [W2[0..19][g], b2[g], W3[g]]
//  [640]     : b3
// word stride per o-lane = 1284 ; 1284 mod 32 = 4 -> the 8 o-lanes' 8B chunks
// start at banks {0,4,...,28}+c : conflict-free LDS.64, other 24 lanes broadcast.
#define OSTRIDE 642
#define OTILE   8
#define SMEM_PAIRS (OTILE * OSTRIDE)
#define SMEM_BYTES (SMEM_PAIRS * 8)

static __device__ __forceinline__ ull pack2(float lo, float hi) {
    ull r; asm("mov.b64 %0, {%1, %2};" : "=l"(r) : "f"(lo), "f"(hi)); return r;
}
static __device__ __forceinline__ float2 unpack2(ull v) {
    float2 f; asm("mov.b64 {%0, %1}, %2;" : "=f"(f.x), "=f"(f.y) : "l"(v)); return f;
}
static __device__ __forceinline__ ull dup2(float f) {
    ull r; asm("mov.b64 %0, {%1, %1};" : "=l"(r) : "f"(f)); return r;
}
static __device__ __forceinline__ ull fma2(ull a, ull b, ull c) {
    ull d; asm("fma.rn.f32x2 %0, %1, %2, %3;" : "=l"(d) : "l"(a), "l"(b), "l"(c)); return d;
}
static __device__ __forceinline__ ull mul2(ull a, ull b) {
    ull d; asm("mul.rn.f32x2 %0, %1, %2;" : "=l"(d) : "l"(a), "l"(b)); return d;
}
static __device__ __forceinline__ ull add2(ull a, ull b) {
    ull d; asm("add.rn.f32x2 %0, %1, %2;" : "=l"(d) : "l"(a), "l"(b)); return d;
}
static __device__ __forceinline__ float ex2_f(float x) {
    float r; asm("ex2.approx.f32 %0, %1;" : "=f"(r) : "f"(x)); return r;
}
static __device__ __forceinline__ float rcp_f(float x) {
    float r; asm("rcp.approx.f32 %0, %1;" : "=f"(r) : "f"(x)); return r;
}

// tanh(x) = 1 - 2/(exp(2x)+1)  (exact limits at +/-inf; ~2ulp interior)
static __device__ __forceinline__ ull tanh2(ull v) {
    const ull C2   = dup2(2.8853900817779268f);  // 2*log2(e)
    const ull ONE2 = dup2(1.0f);
    const ull M2   = dup2(-2.0f);
    ull m = mul2(v, C2);
    float2 mf = unpack2(m);
    float e0 = ex2_f(mf.x);
    float e1 = ex2_f(mf.y);
    ull s = add2(pack2(e0, e1), ONE2);
    float2 sf = unpack2(s);
    float r0 = rcp_f(sf.x);
    float r1 = rcp_f(sf.y);
    return fma2(pack2(r0, r1), M2, ONE2);
}

__global__ void __launch_bounds__(128, 4)
medil_kernel(const float* __restrict__ x,
             const float* __restrict__ noise,
             const int*   __restrict__ cause,
             const float* __restrict__ W1,
             const float* __restrict__ b1,
             const float* __restrict__ W2,
             const float* __restrict__ b2,
             const float* __restrict__ W3,
             const float* __restrict__ b3,
             float*       __restrict__ out)
{
    extern __shared__ ull wsm[];
    const int tid   = threadIdx.x;
    const int oBase = blockIdx.x * OTILE;

    // ---- preamble: stage transposed dup-pair weights for 8 o's ----
#pragma unroll 1
    for (int ol = 0; ol < OTILE; ++ol) {
        const int o = oBase + ol;
        ull* dst = wsm + ol * OSTRIDE;
#pragma unroll 1
        for (int off = tid; off <= 640; off += 128) {
            float v;
            if (off < 200) {
                int j = off / 10;
                int r = off - j * 10;
                v = (r < 9) ? W1[o * 180 + r * 20 + j] : b1[o * 20 + j];
            } else if (off < 640) {
                int t = off - 200;
                int g = t / 22;
                int r = t - g * 22;
                if      (r < 20)  v = W2[o * 400 + r * 20 + g];
                else if (r == 20) v = b2[o * 20 + g];
                else              v = W3[o * 20 + g];
            } else {
                v = b3[o];
            }
            dst[off] = pack2(v, v);
        }
    }
    __syncthreads();

    const int o  = oBase + (tid & 7);
    const ull* wb = wsm + (tid & 7) * OSTRIDE;

    int c[KK];
    {
        int4 cA = *(const int4*)(cause + o * KK);
        int4 cB = *(const int4*)(cause + o * KK + 4);
        c[0] = cA.x; c[1] = cA.y; c[2] = cA.z; c[3] = cA.w;
        c[4] = cB.x; c[5] = cB.y; c[6] = cB.z; c[7] = cB.w;
    }

    const int bThread = blockIdx.y * 256 + (tid >> 3) * 2;  // this thread's first b

#pragma unroll 1
    for (int it = 0; it < 8; ++it) {
        const int b0 = bThread + it * 32;
        const float* xr = x + b0 * LL;

        // gather: inp[0] = noise pair, inp[k+1] = x[b, cause[o,k]] pair
        ull inp[KK + 1];
        inp[0] = pack2(noise[b0 * OO + o], noise[(b0 + 1) * OO + o]);
#pragma unroll
        for (int k = 0; k < KK; k++)
            inp[k + 1] = pack2(xr[c[k]], xr[LL + c[k]]);

        // ---- layer 1: h[j] = tanh(b1[j] + sum_i inp[i]*W1[i][j]) ----
        ull h[HH];
#pragma unroll
        for (int j = 0; j < HH; j++) {
            const ull* wj = wb + j * 10;
            ull a = wj[9];                 // b1[j]
#pragma unroll
            for (int i = 0; i < KK + 1; i++)
                a = fma2(inp[i], wj[i], a);
            h[j] = tanh2(a);
        }

        // ---- layers 2+3 fused: acc += tanh(b2[g] + sum_j h[j]*W2[j][g]) * W3[g] ----
        ull acc = wb[640];                 // b3
#pragma unroll
        for (int g = 0; g < HH; g++) {
            const ull* wg = wb + 200 + g * 22;
            ull p = wg[20];                // b2[g]
#pragma unroll
            for (int j = 0; j < HH; j++)
                p = fma2(h[j], wg[j], p);
            acc = fma2(tanh2(p), wg[21], acc);  // * W3[g]
        }

        float2 r = unpack2(acc);
        out[b0 * OO + o]       = r.x;
        out[(b0 + 1) * OO + o] = r.y;
    }
}

extern "C" void kernel_launch(void* const* d_in, const int* in_sizes, int n_in,
                              void* d_out, int out_size)
{
    const float* x     = (const float*)d_in[0];
    const float* noise = (const float*)d_in[1];
    const int*   cause = (const int*)  d_in[2];
    const float* W1    = (const float*)d_in[3];
    const float* b1    = (const float*)d_in[4];
    const float* W2    = (const float*)d_in[5];
    const float* b2    = (const float*)d_in[6];
    const float* W3    = (const float*)d_in[7];
    const float* b3    = (const float*)d_in[8];
    float* out = (float*)d_out;

    // Allow 4 CTAs x 41KB shared per SM (prefer shared over L1 carveout).
    cudaFuncSetAttribute(medil_kernel,
                         cudaFuncAttributePreferredSharedMemoryCarveout,
                         cudaSharedmemCarveoutMaxShared);

    dim3 grid(OO / OTILE, BB / 256);   // (64, 32) = 2048 blocks
    medil_kernel<<<grid, 128, SMEM_BYTES>>>(x, noise, cause, W1, b1, W2, b2, W3, b3, out);
}

// round 5
// speedup vs baseline: 5.6242x; 5.6242x over previous
#include <cuda_runtime.h>
#include <cstdint>

#define BB    8192
#define LL    128
#define OO    512
#define KK    8
#define HH    20

#define OTILE   8      // o's per block, one per warp
#define BTILE   32     // b's per tile, one per lane
#define NTILES  8      // b-tiles per block
#define XPAD    129    // x tile row pitch (floats): bank(lane*129+c) = (lane+c)%32, conflict-free
#define WSTRIDE 641    // floats per o: [0,200)=20x{W1[0..8][j],b1[j]}, [200,640)=20x{W2[.][g],b2[g],W3[g]}, [640]=b3

static __device__ __forceinline__ float ex2_f(float x) {
    float r; asm("ex2.approx.f32 %0, %1;" : "=f"(r) : "f"(x)); return r;
}
static __device__ __forceinline__ float rcp_f(float x) {
    float r; asm("rcp.approx.f32 %0, %1;" : "=f"(r) : "f"(x)); return r;
}
// tanh(x) = 1 - 2/(exp(2x)+1): exact limits at +/-inf, ~2ulp interior
static __device__ __forceinline__ float tanh_fast(float x) {
    float e = ex2_f(x * 2.8853900817779268f);   // exp(2x) = 2^(2*log2e*x)
    float r = rcp_f(e + 1.0f);
    return fmaf(r, -2.0f, 1.0f);
}

__global__ void __launch_bounds__(256, 3)
medil_kernel(const float* __restrict__ x,
             const float* __restrict__ noise,
             const int*   __restrict__ cause,
             const float* __restrict__ W1,
             const float* __restrict__ b1,
             const float* __restrict__ W2,
             const float* __restrict__ b2,
             const float* __restrict__ W3,
             const float* __restrict__ b3,
             float*       __restrict__ out)
{
    __shared__ float wsm[OTILE * WSTRIDE];   // 20.5 KB
    __shared__ float xsm[BTILE * XPAD];      // 16.5 KB

    const int tid  = threadIdx.x;
    const int lane = tid & 31;
    const int warp = tid >> 5;
    const int oBase = blockIdx.x * OTILE;

    // ---- stage transposed weights for 8 o's (scalar floats) ----
#pragma unroll 1
    for (int idx = tid; idx < OTILE * WSTRIDE; idx += 256) {
        int ol  = idx / WSTRIDE;
        int off = idx - ol * WSTRIDE;
        int o   = oBase + ol;
        float v;
        if (off < 200) {
            int j = off / 10;
            int r = off - j * 10;
            v = (r < 9) ? W1[o * 180 + r * 20 + j] : b1[o * 20 + j];
        } else if (off < 640) {
            int t = off - 200;
            int g = t / 22;
            int r = t - g * 22;
            if      (r < 20)  v = W2[o * 400 + r * 20 + g];
            else if (r == 20) v = b2[o * 20 + g];
            else              v = W3[o * 20 + g];
        } else {
            v = b3[o];
        }
        wsm[idx] = v;
    }

    const int o = oBase + warp;                 // this warp's output unit
    const float* wb = wsm + warp * WSTRIDE;

    int c[KK];
    {
        int4 cA = *(const int4*)(cause + o * KK);
        int4 cB = *(const int4*)(cause + o * KK + 4);
        c[0] = cA.x; c[1] = cA.y; c[2] = cA.z; c[3] = cA.w;
        c[4] = cB.x; c[5] = cB.y; c[6] = cB.z; c[7] = cB.w;
    }

    const int bBlock = blockIdx.y * (NTILES * BTILE);

#pragma unroll 1
    for (int t = 0; t < NTILES; ++t) {
        const int b0 = bBlock + t * BTILE;

        __syncthreads();   // xsm reuse barrier (also orders wsm writes on t==0)

        // ---- stage x tile [32 b x 128 L] coalesced; pad rows to 129 ----
        {
            int row  = tid >> 3;
            int col0 = (tid & 7) * 16;
            const float4* src = (const float4*)(x + (size_t)(b0 + row) * LL + col0);
            float* dst = xsm + row * XPAD + col0;
#pragma unroll
            for (int q = 0; q < 4; q++) {
                float4 v = src[q];
                dst[q * 4 + 0] = v.x;
                dst[q * 4 + 1] = v.y;
                dst[q * 4 + 2] = v.z;
                dst[q * 4 + 3] = v.w;
            }
        }
        __syncthreads();

        const int b = b0 + lane;

        // ---- inputs: noise + 8 smem gathers (conflict-free via pad) ----
        float inp[KK + 1];
        inp[0] = noise[(size_t)b * OO + o];
        const float* xr = xsm + lane * XPAD;
#pragma unroll
        for (int k = 0; k < KK; k++) inp[k + 1] = xr[c[k]];

        // ---- layer 1: h[j] = tanh(b1[j] + sum_i inp[i]*W1[i][j]) ----
        float h[HH];
#pragma unroll 2
        for (int j = 0; j < HH; j++) {
            const float* wj = wb + j * 10;
            float a = wj[9];
#pragma unroll
            for (int i = 0; i < KK + 1; i++)
                a = fmaf(inp[i], wj[i], a);
            h[j] = tanh_fast(a);
        }

        // ---- layers 2+3 fused: acc += tanh(b2[g] + sum_j h[j]*W2[j][g]) * W3[g] ----
        float acc = wb[640];
#pragma unroll 2
        for (int g = 0; g < HH; g++) {
            const float* wg = wb + 200 + g * 22;
            float p = wg[20];
#pragma unroll
            for (int j = 0; j < HH; j++)
                p = fmaf(h[j], wg[j], p);
            acc = fmaf(tanh_fast(p), wg[21], acc);
        }

        out[(size_t)b * OO + o] = acc;
    }
}

extern "C" void kernel_launch(void* const* d_in, const int* in_sizes, int n_in,
                              void* d_out, int out_size)
{
    const float* x     = (const float*)d_in[0];
    const float* noise = (const float*)d_in[1];
    const int*   cause = (const int*)  d_in[2];
    const float* W1    = (const float*)d_in[3];
    const float* b1    = (const float*)d_in[4];
    const float* W2    = (const float*)d_in[5];
    const float* b2    = (const float*)d_in[6];
    const float* W3    = (const float*)d_in[7];
    const float* b3    = (const float*)d_in[8];
    float* out = (float*)d_out;

    dim3 grid(OO / OTILE, BB / (NTILES * BTILE));   // (64, 32) = 2048 blocks
    medil_kernel<<<grid, 256>>>(x, noise, cause, W1, b1, W2, b2, W3, b3, out);
}

// round 6
// speedup vs baseline: 7.1762x; 1.2760x over previous
#include <cuda_runtime.h>
#include <cstdint>

#define BB    8192
#define LL    128
#define OO    512
#define KK    8
#define HH    20

#define OTILE   8      // o's per block, one per warp
#define BTILE   32     // b's per tile, one per lane
#define NTILES  8      // b-tiles per block
#define XPAD    129    // x tile row pitch: bank(lane*129+c) = (lane+c)%32, conflict-free

// Per-o weight layout (float4-aligned blocks), stride 724 floats:
//  [0,240)    : 20 blocks of 12: [W1[0..8][j], b1[j], pad, pad]
//  [240,720)  : 20 blocks of 24: [W2[0..19][g], b2[g], W3[g], pad, pad]
//  [720]      : b3  (+3 pad)
#define WSTRIDE 724

static __device__ __forceinline__ float tanh_fast(float x) {
    float r; asm("tanh.approx.f32 %0, %1;" : "=f"(r) : "f"(x)); return r;
}

__global__ void __launch_bounds__(256, 3)
medil_kernel(const float* __restrict__ x,
             const float* __restrict__ noise,
             const int*   __restrict__ cause,
             const float* __restrict__ W1,
             const float* __restrict__ b1,
             const float* __restrict__ W2,
             const float* __restrict__ b2,
             const float* __restrict__ W3,
             const float* __restrict__ b3,
             float*       __restrict__ out)
{
    __shared__ __align__(16) float wsm[OTILE * WSTRIDE];  // 23.2 KB
    __shared__ float xsm[BTILE * XPAD];                   // 16.5 KB

    const int tid  = threadIdx.x;
    const int lane = tid & 31;
    const int warp = tid >> 5;
    const int oBase = blockIdx.x * OTILE;

    // ---- stage transposed, padded weights for 8 o's ----
#pragma unroll 1
    for (int idx = tid; idx < OTILE * WSTRIDE; idx += 256) {
        int ol  = idx / WSTRIDE;
        int off = idx - ol * WSTRIDE;
        int o   = oBase + ol;
        float v = 0.0f;
        if (off < 240) {
            int j = off / 12;
            int r = off - j * 12;
            if      (r < 9)  v = W1[o * 180 + r * 20 + j];
            else if (r == 9) v = b1[o * 20 + j];
        } else if (off < 720) {
            int t = off - 240;
            int g = t / 24;
            int r = t - g * 24;
            if      (r < 20)  v = W2[o * 400 + r * 20 + g];
            else if (r == 20) v = b2[o * 20 + g];
            else if (r == 21) v = W3[o * 20 + g];
        } else if (off == 720) {
            v = b3[o];
        }
        wsm[idx] = v;
    }

    const int o = oBase + warp;                 // this warp's output unit
    const float* wb = wsm + warp * WSTRIDE;

    int c[KK];
    {
        int4 cA = *(const int4*)(cause + o * KK);
        int4 cB = *(const int4*)(cause + o * KK + 4);
        c[0] = cA.x; c[1] = cA.y; c[2] = cA.z; c[3] = cA.w;
        c[4] = cB.x; c[5] = cB.y; c[6] = cB.z; c[7] = cB.w;
    }

    const int bBlock = blockIdx.y * (NTILES * BTILE);

#pragma unroll 1
    for (int t = 0; t < NTILES; ++t) {
        const int b0 = bBlock + t * BTILE;

        __syncthreads();   // xsm reuse barrier (also orders wsm writes on t==0)

        // ---- stage x tile [32 b x 128 L] coalesced; pad rows to 129 ----
        {
            int row  = tid >> 3;
            int col0 = (tid & 7) * 16;
            const float4* src = (const float4*)(x + (size_t)(b0 + row) * LL + col0);
            float* dst = xsm + row * XPAD + col0;
#pragma unroll
            for (int q = 0; q < 4; q++) {
                float4 v = src[q];
                dst[q * 4 + 0] = v.x;
                dst[q * 4 + 1] = v.y;
                dst[q * 4 + 2] = v.z;
                dst[q * 4 + 3] = v.w;
            }
        }
        __syncthreads();

        const int b = b0 + lane;

        // ---- inputs: noise + 8 smem gathers (conflict-free via pad) ----
        float inp[KK + 1];
        inp[0] = noise[(size_t)b * OO + o];
        const float* xr = xsm + lane * XPAD;
#pragma unroll
        for (int k = 0; k < KK; k++) inp[k + 1] = xr[c[k]];

        // ---- layer 1: h[j] = tanh(b1[j] + sum_i inp[i]*W1[i][j]) ----
        float h[HH];
#pragma unroll 1
        for (int j = 0; j < HH; j++) {
            const float4* wj = (const float4*)(wb + j * 12);
            float4 q0 = wj[0];   // W1[0..3][j]
            float4 q1 = wj[1];   // W1[4..7][j]
            float4 q2 = wj[2];   // W1[8][j], b1[j], pad, pad
            float a = q2.y;
            a = fmaf(inp[0], q0.x, a);
            a = fmaf(inp[1], q0.y, a);
            a = fmaf(inp[2], q0.z, a);
            a = fmaf(inp[3], q0.w, a);
            a = fmaf(inp[4], q1.x, a);
            a = fmaf(inp[5], q1.y, a);
            a = fmaf(inp[6], q1.z, a);
            a = fmaf(inp[7], q1.w, a);
            a = fmaf(inp[8], q2.x, a);
            h[j] = tanh_fast(a);
        }

        // ---- layers 2+3 fused: acc += tanh(b2[g] + sum_j h[j]*W2[j][g]) * W3[g] ----
        float acc = wb[720];
#pragma unroll 1
        for (int g = 0; g < HH; g++) {
            const float4* wg = (const float4*)(wb + 240 + g * 24);
            float4 r0 = wg[0];
            float4 r1 = wg[1];
            float4 r2 = wg[2];
            float4 r3 = wg[3];
            float4 r4 = wg[4];
            float4 r5 = wg[5];   // b2[g], W3[g], pad, pad
            float p = r5.x;
            p = fmaf(h[0],  r0.x, p);
            p = fmaf(h[1],  r0.y, p);
            p = fmaf(h[2],  r0.z, p);
            p = fmaf(h[3],  r0.w, p);
            p = fmaf(h[4],  r1.x, p);
            p = fmaf(h[5],  r1.y, p);
            p = fmaf(h[6],  r1.z, p);
            p = fmaf(h[7],  r1.w, p);
            p = fmaf(h[8],  r2.x, p);
            p = fmaf(h[9],  r2.y, p);
            p = fmaf(h[10], r2.z, p);
            p = fmaf(h[11], r2.w, p);
            p = fmaf(h[12], r3.x, p);
            p = fmaf(h[13], r3.y, p);
            p = fmaf(h[14], r3.z, p);
            p = fmaf(h[15], r3.w, p);
            p = fmaf(h[16], r4.x, p);
            p = fmaf(h[17], r4.y, p);
            p = fmaf(h[18], r4.z, p);
            p = fmaf(h[19], r4.w, p);
            acc = fmaf(tanh_fast(p), r5.y, acc);
        }

        out[(size_t)b * OO + o] = acc;
    }
}

extern "C" void kernel_launch(void* const* d_in, const int* in_sizes, int n_in,
                              void* d_out, int out_size)
{
    const float* x     = (const float*)d_in[0];
    const float* noise = (const float*)d_in[1];
    const int*   cause = (const int*)  d_in[2];
    const float* W1    = (const float*)d_in[3];
    const float* b1    = (const float*)d_in[4];
    const float* W2    = (const float*)d_in[5];
    const float* b2    = (const float*)d_in[6];
    const float* W3    = (const float*)d_in[7];
    const float* b3    = (const float*)d_in[8];
    float* out = (float*)d_out;

    dim3 grid(OO / OTILE, BB / (NTILES * BTILE));   // (64, 32) = 2048 blocks
    medil_kernel<<<grid, 256>>>(x, noise, cause, W1, b1, W2, b2, W3, b3, out);
}

// round 7
// speedup vs baseline: 7.5444x; 1.0513x over previous
#include <cuda_runtime.h>
#include <cstdint>

typedef unsigned long long ull;

#define BB    8192
#define LL    128
#define OO    512
#define KK    8
#define HH    20

#define OTILE   8      // o's per block, one per warp
#define BTILE   64     // b's per tile: lane and lane+32 per thread
#define NTILES  8      // b-tiles per block
#define XPAD    129    // x tile row pitch (floats): conflict-free gathers

// Per-o weight layout in DUPLICATED f32x2 pairs, stride 724 pairs:
//  [0,240)   : 20 blocks of 12 pairs: [W1[0..8][j], b1[j], pad, pad]
//  [240,720) : 20 blocks of 24 pairs: [W2[0..19][g], b2[g], W3[g], pad, pad]
//  [720]     : b3
#define WSTRIDE 724
#define WPAIRS  (OTILE * WSTRIDE)
#define XFLOATS (BTILE * XPAD)
#define SMEM_BYTES (WPAIRS * 8 + XFLOATS * 4)

static __device__ __forceinline__ ull pack2(float lo, float hi) {
    ull r; asm("mov.b64 %0, {%1, %2};" : "=l"(r) : "f"(lo), "f"(hi)); return r;
}
static __device__ __forceinline__ float2 unpack2(ull v) {
    float2 f; asm("mov.b64 {%0, %1}, %2;" : "=f"(f.x), "=f"(f.y) : "l"(v)); return f;
}
static __device__ __forceinline__ ull fma2(ull a, ull b, ull c) {
    ull d; asm("fma.rn.f32x2 %0, %1, %2, %3;" : "=l"(d) : "l"(a), "l"(b), "l"(c)); return d;
}
static __device__ __forceinline__ float tanh_f(float x) {
    float r; asm("tanh.approx.f32 %0, %1;" : "=f"(r) : "f"(x)); return r;
}
static __device__ __forceinline__ ull tanh2(ull v) {
    float2 f = unpack2(v);
    return pack2(tanh_f(f.x), tanh_f(f.y));
}

__global__ void __launch_bounds__(256, 2)
medil_kernel(const float* __restrict__ x,
             const float* __restrict__ noise,
             const int*   __restrict__ cause,
             const float* __restrict__ W1,
             const float* __restrict__ b1,
             const float* __restrict__ W2,
             const float* __restrict__ b2,
             const float* __restrict__ W3,
             const float* __restrict__ b3,
             float*       __restrict__ out)
{
    extern __shared__ __align__(16) char smem_raw[];
    ull*   wsm = (ull*)smem_raw;                       // 46.3 KB dup pairs
    float* xsm = (float*)(smem_raw + WPAIRS * 8);      // 33 KB x tile

    const int tid  = threadIdx.x;
    const int lane = tid & 31;
    const int warp = tid >> 5;
    const int oBase = blockIdx.x * OTILE;

    // ---- stage transposed, padded, duplicated weight pairs for 8 o's ----
#pragma unroll 1
    for (int idx = tid; idx < WPAIRS; idx += 256) {
        int ol  = idx / WSTRIDE;
        int off = idx - ol * WSTRIDE;
        int o   = oBase + ol;
        float v = 0.0f;
        if (off < 240) {
            int j = off / 12;
            int r = off - j * 12;
            if      (r < 9)  v = W1[o * 180 + r * 20 + j];
            else if (r == 9) v = b1[o * 20 + j];
        } else if (off < 720) {
            int t = off - 240;
            int g = t / 24;
            int r = t - g * 24;
            if      (r < 20)  v = W2[o * 400 + r * 20 + g];
            else if (r == 20) v = b2[o * 20 + g];
            else if (r == 21) v = W3[o * 20 + g];
        } else if (off == 720) {
            v = b3[o];
        }
        wsm[idx] = pack2(v, v);
    }

    const int o = oBase + warp;                 // this warp's output unit
    const ull* wb = wsm + warp * WSTRIDE;

    int c[KK];
    {
        int4 cA = *(const int4*)(cause + o * KK);
        int4 cB = *(const int4*)(cause + o * KK + 4);
        c[0] = cA.x; c[1] = cA.y; c[2] = cA.z; c[3] = cA.w;
        c[4] = cB.x; c[5] = cB.y; c[6] = cB.z; c[7] = cB.w;
    }

    const int bBlock = blockIdx.y * (NTILES * BTILE);

#pragma unroll 1
    for (int t = 0; t < NTILES; ++t) {
        const int b0 = bBlock + t * BTILE;

        __syncthreads();   // xsm reuse barrier (also orders wsm writes on t==0)

        // ---- stage x tile [64 b x 128 L] coalesced; pad rows to 129 ----
        {
            int row  = tid >> 2;          // 0..63
            int col0 = (tid & 3) * 32;    // 0,32,64,96
            const float4* src = (const float4*)(x + (size_t)(b0 + row) * LL + col0);
            float* dst = xsm + row * XPAD + col0;
#pragma unroll
            for (int q = 0; q < 8; q++) {
                float4 v = src[q];
                dst[q * 4 + 0] = v.x;
                dst[q * 4 + 1] = v.y;
                dst[q * 4 + 2] = v.z;
                dst[q * 4 + 3] = v.w;
            }
        }
        __syncthreads();

        const int bA = b0 + lane;        // pair of b's per thread
        const int bB = bA + 32;

        // ---- inputs: noise + 8 gathers per b (conflict-free, pad 129) ----
        ull inp[KK + 1];
        inp[0] = pack2(noise[(size_t)bA * OO + o], noise[(size_t)bB * OO + o]);
        const float* xr0 = xsm + lane * XPAD;
        const float* xr1 = xr0 + 32 * XPAD;
#pragma unroll
        for (int k = 0; k < KK; k++)
            inp[k + 1] = pack2(xr0[c[k]], xr1[c[k]]);

        // ---- layer 1: h[j] = tanh(b1[j] + sum_i inp[i]*W1[i][j]) ----
        ull h[HH];
#pragma unroll 1
        for (int j = 0; j < HH; j++) {
            const ulonglong2* wj = (const ulonglong2*)(wb + j * 12);
            ulonglong2 q0 = wj[0];
            ulonglong2 q1 = wj[1];
            ulonglong2 q2 = wj[2];
            ulonglong2 q3 = wj[3];
            ulonglong2 q4 = wj[4];   // W1[8][j], b1[j]
            ull a = q4.y;
            a = fma2(inp[0], q0.x, a);
            a = fma2(inp[1], q0.y, a);
            a = fma2(inp[2], q1.x, a);
            a = fma2(inp[3], q1.y, a);
            a = fma2(inp[4], q2.x, a);
            a = fma2(inp[5], q2.y, a);
            a = fma2(inp[6], q3.x, a);
            a = fma2(inp[7], q3.y, a);
            a = fma2(inp[8], q4.x, a);
            h[j] = tanh2(a);
        }

        // ---- layers 2+3 fused: acc += tanh(b2[g] + sum_j h[j]*W2[j][g]) * W3[g] ----
        ull acc = wb[720];               // b3 pair
#pragma unroll 1
        for (int g = 0; g < HH; g++) {
            const ulonglong2* wg = (const ulonglong2*)(wb + 240 + g * 24);
            ull p;
            {
                ulonglong2 w0 = wg[0];
                p = fma2(h[0], w0.x, fma2(h[1], w0.y, wg[10].x));  // includes b2[g]
            }
#pragma unroll
            for (int q = 1; q < 10; q++) {
                ulonglong2 w = wg[q];
                p = fma2(h[2 * q],     w.x, p);
                p = fma2(h[2 * q + 1], w.y, p);
            }
            acc = fma2(tanh2(p), wg[10].y, acc);   // * W3[g]
        }

        float2 r = unpack2(acc);
        out[(size_t)bA * OO + o] = r.x;
        out[(size_t)bB * OO + o] = r.y;
    }
}

extern "C" void kernel_launch(void* const* d_in, const int* in_sizes, int n_in,
                              void* d_out, int out_size)
{
    const float* x     = (const float*)d_in[0];
    const float* noise = (const float*)d_in[1];
    const int*   cause = (const int*)  d_in[2];
    const float* W1    = (const float*)d_in[3];
    const float* b1    = (const float*)d_in[4];
    const float* W2    = (const float*)d_in[5];
    const float* b2    = (const float*)d_in[6];
    const float* W3    = (const float*)d_in[7];
    const float* b3    = (const float*)d_in[8];
    float* out = (float*)d_out;

    cudaFuncSetAttribute(medil_kernel,
                         cudaFuncAttributeMaxDynamicSharedMemorySize, SMEM_BYTES);

    dim3 grid(OO / OTILE, BB / (NTILES * BTILE));   // (64, 16) = 1024 blocks
    medil_kernel<<<grid, 256, SMEM_BYTES>>>(x, noise, cause, W1, b1, W2, b2, W3, b3, out);
}